// round 2
// baseline (speedup 1.0000x reference)
#include <cuda_runtime.h>
#include <cuda_bf16.h>

#define D_MODEL 4096
#define NUM_EXPERTS 64
#define TOP_K 2
#define N_TOKENS (4 * 4096)          // B*S = 16384

#define M_TILE 128
#define BK 32
#define THREADS_GEMM 256
// thread tile: 8 tokens (stride-16 interleaved) x 4 experts

#define XS_LD (M_TILE + 1)           // padded row to kill store-bank conflicts

// ---------------------------------------------------------------------------
// Kernel 1: logits = x @ W + b   (fp32 FFMA GEMM, M=16384, N=64, K=4096)
// Writes raw logits into the probs region of d_out; kernel 2 converts in place.
// ---------------------------------------------------------------------------
__global__ __launch_bounds__(THREADS_GEMM, 1)
void router_gemm_kernel(const float* __restrict__ x,
                        const float* __restrict__ W,
                        const float* __restrict__ b,
                        float* __restrict__ logits_out)
{
    __shared__ float xs[BK * XS_LD];      // [k][m], padded
    __shared__ float ws[BK * NUM_EXPERTS];

    const int tid = threadIdx.x;
    const int m0  = blockIdx.x * M_TILE;

    const int tm = tid & 15;      // token-group 0..15 (tokens tm + 16*i)
    const int te = tid >> 4;      // expert-group 0..15 (experts te*4 .. te*4+3)

    float acc[8][4];
#pragma unroll
    for (int i = 0; i < 8; i++)
#pragma unroll
        for (int j = 0; j < 4; j++) acc[i][j] = 0.0f;

    // global-load mapping for x chunk: row = tid/8 (+32 per iter), kk = (tid%8)*4
    const int xl_row = tid >> 3;
    const int xl_kk  = (tid & 7) * 4;

    for (int kc = 0; kc < D_MODEL; kc += BK) {
        // --- load x tile [M_TILE][BK] -> xs[k][m] (transposed, padded) ---
#pragma unroll
        for (int r = 0; r < 4; r++) {
            int m = xl_row + r * 32;
            float4 v = *reinterpret_cast<const float4*>(
                &x[(size_t)(m0 + m) * D_MODEL + kc + xl_kk]);
            xs[(xl_kk + 0) * XS_LD + m] = v.x;
            xs[(xl_kk + 1) * XS_LD + m] = v.y;
            xs[(xl_kk + 2) * XS_LD + m] = v.z;
            xs[(xl_kk + 3) * XS_LD + m] = v.w;
        }
        // --- load W chunk [BK][64] (row-major, contiguous) ---
#pragma unroll
        for (int r = 0; r < 2; r++) {
            int idx4 = tid + r * 256;                 // float4 index, 512 total
            float4 v = *reinterpret_cast<const float4*>(
                &W[(size_t)(kc) * NUM_EXPERTS + idx4 * 4]);
            *reinterpret_cast<float4*>(&ws[idx4 * 4]) = v;
        }
        __syncthreads();

#pragma unroll
        for (int k = 0; k < BK; k++) {
            float4 w4 = *reinterpret_cast<const float4*>(&ws[k * NUM_EXPERTS + te * 4]);
            float a[8];
#pragma unroll
            for (int i = 0; i < 8; i++) a[i] = xs[k * XS_LD + tm + 16 * i];
#pragma unroll
            for (int i = 0; i < 8; i++) {
                acc[i][0] = fmaf(a[i], w4.x, acc[i][0]);
                acc[i][1] = fmaf(a[i], w4.y, acc[i][1]);
                acc[i][2] = fmaf(a[i], w4.z, acc[i][2]);
                acc[i][3] = fmaf(a[i], w4.w, acc[i][3]);
            }
        }
        __syncthreads();
    }

    // epilogue: add bias, write logits
    float4 bias = *reinterpret_cast<const float4*>(&b[te * 4]);
#pragma unroll
    for (int i = 0; i < 8; i++) {
        int token = m0 + tm + 16 * i;
        float4 o;
        o.x = acc[i][0] + bias.x;
        o.y = acc[i][1] + bias.y;
        o.z = acc[i][2] + bias.z;
        o.w = acc[i][3] + bias.w;
        *reinterpret_cast<float4*>(&logits_out[(size_t)token * NUM_EXPERTS + te * 4]) = o;
    }
}

// ---------------------------------------------------------------------------
// Kernel 2: per-token softmax + top-2 (+ renormalize). One warp per token.
// Reads logits from probs region, overwrites with probs, writes topk sections.
// ---------------------------------------------------------------------------
__device__ __forceinline__ bool gt_pair(float va, int ia, float vb, int ib) {
    return (va > vb) || (va == vb && ia < ib);
}

__global__ void router_softmax_topk_kernel(float* __restrict__ probs,       // [N_TOKENS][64]
                                           float* __restrict__ topk_p,      // [N_TOKENS][2]
                                           float* __restrict__ topk_i)      // [N_TOKENS][2]
{
    const int warp_id = (blockIdx.x * blockDim.x + threadIdx.x) >> 5;
    const int lane    = threadIdx.x & 31;
    if (warp_id >= N_TOKENS) return;

    float* row = probs + (size_t)warp_id * NUM_EXPERTS;
    float l0 = row[lane];
    float l1 = row[lane + 32];

    // max reduce
    float m = fmaxf(l0, l1);
#pragma unroll
    for (int off = 16; off > 0; off >>= 1)
        m = fmaxf(m, __shfl_xor_sync(0xFFFFFFFFu, m, off));

    float e0 = __expf(l0 - m);
    float e1 = __expf(l1 - m);
    float s = e0 + e1;
#pragma unroll
    for (int off = 16; off > 0; off >>= 1)
        s += __shfl_xor_sync(0xFFFFFFFFu, s, off);

    float inv = 1.0f / s;
    float p0 = e0 * inv;
    float p1 = e1 * inv;
    row[lane]      = p0;
    row[lane + 32] = p1;

    // local sorted top-2 (tie -> lower index, which is lane here)
    float v0, v1; int i0, i1;
    if (gt_pair(p0, lane, p1, lane + 32)) { v0 = p0; i0 = lane;      v1 = p1; i1 = lane + 32; }
    else                                  { v0 = p1; i0 = lane + 32; v1 = p0; i1 = lane; }

    // butterfly merge of sorted top-2 pairs
#pragma unroll
    for (int off = 16; off > 0; off >>= 1) {
        float ov0 = __shfl_xor_sync(0xFFFFFFFFu, v0, off);
        float ov1 = __shfl_xor_sync(0xFFFFFFFFu, v1, off);
        int   oi0 = __shfl_xor_sync(0xFFFFFFFFu, i0, off);
        int   oi1 = __shfl_xor_sync(0xFFFFFFFFu, i1, off);
        float nv0, nv1; int ni0, ni1;
        if (gt_pair(v0, i0, ov0, oi0)) {
            nv0 = v0; ni0 = i0;
            if (gt_pair(ov0, oi0, v1, i1)) { nv1 = ov0; ni1 = oi0; }
            else                           { nv1 = v1;  ni1 = i1;  }
        } else {
            nv0 = ov0; ni0 = oi0;
            if (gt_pair(v0, i0, ov1, oi1)) { nv1 = v0;  ni1 = i0;  }
            else                           { nv1 = ov1; ni1 = oi1; }
        }
        v0 = nv0; v1 = nv1; i0 = ni0; i1 = ni1;
    }

    if (lane == 0) {
        float denom = 1.0f / (v0 + v1 + 1e-9f);
        topk_p[(size_t)warp_id * 2 + 0] = v0 * denom;
        topk_p[(size_t)warp_id * 2 + 1] = v1 * denom;
        topk_i[(size_t)warp_id * 2 + 0] = (float)i0;
        topk_i[(size_t)warp_id * 2 + 1] = (float)i1;
    }
}

// ---------------------------------------------------------------------------
extern "C" void kernel_launch(void* const* d_in, const int* in_sizes, int n_in,
                              void* d_out, int out_size)
{
    const float* x = (const float*)d_in[0];
    const float* W = (const float*)d_in[1];
    const float* b = (const float*)d_in[2];

    float* out = (float*)d_out;
    float* probs  = out;                                       // 16384*64
    float* topk_p = out + (size_t)N_TOKENS * NUM_EXPERTS;      // 16384*2
    float* topk_i = topk_p + (size_t)N_TOKENS * TOP_K;         // 16384*2

    router_gemm_kernel<<<N_TOKENS / M_TILE, THREADS_GEMM>>>(x, W, b, probs);

    // one warp per token, 8 warps (256 threads) per block
    router_softmax_topk_kernel<<<N_TOKENS / 8, 256>>>(probs, topk_p, topk_i);
}